// round 5
// baseline (speedup 1.0000x reference)
#include <cuda_runtime.h>
#include <cuda_bf16.h>
#include <math.h>

// B=8, D=64, T=512, O=256 (fixed by the reference)
#define PB 8
#define PD 64
#define PT 512
#define PO 256
#define THREADS 128
#define THALF 256          // t-points per block (T/2)

typedef unsigned long long u64;

// Partial sums workspace: [t-half][(b*D+d)*O+o] = {sw1, sy1, sw2, sy2}
__device__ float4 g_part[2][PB * PD * PO];

__device__ __forceinline__ float ex2a(float x) {
    float y; asm("ex2.approx.ftz.f32 %0, %1;" : "=f"(y) : "f"(x)); return y;
}
__device__ __forceinline__ float lg2a(float x) {
    float y; asm("lg2.approx.ftz.f32 %0, %1;" : "=f"(y) : "f"(x)); return y;
}
__device__ __forceinline__ u64 pk2(float lo, float hi) {
    u64 r; asm("mov.b64 %0, {%1, %2};" : "=l"(r) : "f"(lo), "f"(hi)); return r;
}
__device__ __forceinline__ void upk2(u64 v, float& lo, float& hi) {
    asm("mov.b64 {%0, %1}, %2;" : "=f"(lo), "=f"(hi) : "l"(v));
}
__device__ __forceinline__ u64 fma2(u64 a, u64 b, u64 c) {
    u64 d; asm("fma.rn.f32x2 %0, %1, %2, %3;" : "=l"(d) : "l"(a), "l"(b), "l"(c)); return d;
}
__device__ __forceinline__ u64 mul2(u64 a, u64 b) {
    u64 d; asm("mul.rn.f32x2 %0, %1, %2;" : "=l"(d) : "l"(a), "l"(b)); return d;
}
__device__ __forceinline__ u64 add2(u64 a, u64 b) {
    u64 d; asm("add.rn.f32x2 %0, %1, %2;" : "=l"(d) : "l"(a), "l"(b)); return d;
}

__global__ __launch_bounds__(THREADS, 16)
void interp_partial_kernel(const float* __restrict__ x,
                           const float* __restrict__ grid,
                           const float* __restrict__ kern) {
    // 2048 blocks: (b, d, o-half, t-half). 128 threads, one output column each,
    // summing over this block's 256 t-points.
    const int bid = blockIdx.x;
    const int th  = bid & 1;                  // t-half
    const int oh  = (bid >> 1) & 1;           // o-half
    const int d   = (bid >> 2) & (PD - 1);
    const int b   = bid >> 8;
    const int tid  = threadIdx.x;
    const int lane = tid & 31;
    const int wid  = tid >> 5;                // 0..3, owns 64 t-points

    // Per-warp compacted segments (warp w owns local t in [64w, 64w+64)).
    __shared__ __align__(16) float sA[THALF];  // c1*t^2
    __shared__ __align__(16) float sB[THALF];  // -2*c1*t
    __shared__ __align__(16) float sV[THALF];  // vals
    __shared__ int scnt[4];

    const size_t xoff = (size_t)(b * 3 * PD + d) * PT + th * THALF;
    const float* vp = x + xoff;
    const float* mp = x + xoff + (size_t)PD * PT;
    const float* tp = x + xoff + (size_t)(2 * PD) * PT;

    const float k = kern[d];
    const float alpha = (k > 20.0f) ? k : log1pf(__expf(k));
    const float c1 = -alpha * 1.4426950408889634f;   // -alpha*log2(e)

    // ---- Warp-private compaction: active points have m == 1 exactly ----
    {
        const int tbase = wid * 64;
        int cnt = 0;
        #pragma unroll
        for (int r = 0; r < 2; r++) {
            const int t = tbase + r * 32 + lane;
            const float mv = mp[t];
            const float tv = tp[t];
            const float vv = vp[t];
            const bool act = (mv > 0.5f);
            const unsigned bal = __ballot_sync(0xffffffffu, act);
            if (act) {
                const int idx = tbase + cnt + __popc(bal & ((1u << lane) - 1u));
                sA[idx] = c1 * tv * tv;
                sB[idx] = -2.0f * c1 * tv;
                sV[idx] = vv;
            }
            cnt += __popc(bal);
        }
        const int cpad = (cnt + 3) & ~3;   // multiple of 4, <= 64
        for (int i = cnt + lane; i < cpad; i += 32) {
            sA[tbase + i] = -160.0f;       // 2^-160 -> FTZ 0: zero weight
            sB[tbase + i] = 0.0f;
            sV[tbase + i] = 0.0f;
        }
        if (lane == 0) scnt[wid] = cpad;
    }
    __syncthreads();

    const int o = oh * 128 + tid;
    const float g = grid[b * PO + o];
    const u64 gg = pk2(g, g);

    u64 aw1 = 0, ay1 = 0, aw2 = 0, ay2 = 0;

    #pragma unroll
    for (int seg = 0; seg < 4; seg++) {
        const int base = seg * 64;
        const int ns = scnt[seg];
        for (int i = 0; i < ns; i += 4) {
            #pragma unroll
            for (int p = 0; p < 2; p++) {
                const int idx = base + i + 2 * p;
                const u64 Ap = *(const u64*)(sA + idx);   // packed point pair
                const u64 Bp = *(const u64*)(sB + idx);
                const u64 Vp = *(const u64*)(sV + idx);
                const u64 arg = fma2(Bp, gg, Ap);         // c1(t-g)^2 - c1 g^2
                float a0, a1; upk2(arg, a0, a1);
                const u64 E1 = pk2(ex2a(a0), ex2a(a1));
                const u64 s2 = mul2(E1, E1);
                const u64 s4 = mul2(s2, s2);
                const u64 s8 = mul2(s4, s4);
                const u64 E2 = mul2(s8, s2);              // e1^10 (logm == 0)
                aw1 = add2(aw1, E1);
                ay1 = fma2(E1, Vp, ay1);
                aw2 = add2(aw2, E2);
                ay2 = fma2(E2, Vp, ay2);
            }
        }
    }

    float w1l, w1h, y1l, y1h, w2l, w2h, y2l, y2h;
    upk2(aw1, w1l, w1h); upk2(ay1, y1l, y1h);
    upk2(aw2, w2l, w2h); upk2(ay2, y2l, y2h);

    const int i = (b * PD + d) * PO + o;
    g_part[th][i] = make_float4(w1l + w1h, y1l + y1h, w2l + w2h, y2l + y2h);
}

__global__ __launch_bounds__(PO, 8)
void interp_combine_kernel(const float* __restrict__ grid,
                           const float* __restrict__ kern,
                           float* __restrict__ out) {
    const int bd = blockIdx.x;      // 0..511 = b*PD + d
    const int b  = bd >> 6;
    const int d  = bd & (PD - 1);
    const int o  = threadIdx.x;
    const int i  = bd * PO + o;

    const float4 p0 = g_part[0][i];
    const float4 p1 = g_part[1][i];
    const float sw1 = p0.x + p1.x;
    const float sy1 = p0.y + p1.y;
    const float sw2 = p0.z + p1.z;
    const float sy2 = p0.w + p1.w;

    const float k = kern[d];
    const float alpha = (k > 20.0f) ? k : log1pf(__expf(k));
    const float c1 = -alpha * 1.4426950408889634f;
    const float g = grid[b * PO + o];

    const float w = (lg2a(sw1) + c1 * g * g) * 0.6931471805599453f;

    float* ob = out + (size_t)(b * 3 * PD) * PO + o;
    ob[(size_t)(d) * PO]          = __fdividef(sy1, sw1);  // y
    ob[(size_t)(PD + d) * PO]     = w;                     // w (logsumexp)
    ob[(size_t)(2 * PD + d) * PO] = __fdividef(sy2, sw2);  // y_trans
}

extern "C" void kernel_launch(void* const* d_in, const int* in_sizes, int n_in,
                              void* d_out, int out_size) {
    const float* x    = (const float*)d_in[0];   // (8, 192, 512)
    const float* grid = (const float*)d_in[1];   // (8, 256)
    const float* kern = (const float*)d_in[2];   // (64,)
    float* out = (float*)d_out;                  // (8, 192, 256)

    interp_partial_kernel<<<PB * PD * 4, THREADS>>>(x, grid, kern);
    interp_combine_kernel<<<PB * PD, PO>>>(grid, kern, out);
}